// round 4
// baseline (speedup 1.0000x reference)
#include <cuda_runtime.h>

#define BB     4
#define CC     32
#define HH     512
#define WW     512
#define NBOX   64
#define H_OUT_ 16
#define MAX_W_ 192
#define HW     (HH * WW)
#define CHALF  16

// One block per (bn, i, channel-half): 8192 blocks x 192 threads, each block
// does one output row for 16 channels (R3 winner). R4: channel loop processes
// 2 channels per iteration with all 8 gathers issued before any FMA consumes
// them -> steady-state MLP ~8 per thread (was ~4), halving exposed DRAM
// latency while keeping regs low enough for ~75% occupancy.
__global__ __launch_bounds__(MAX_W_) void roirotate_kernel(
    const float* __restrict__ img,      // (B, C, H, W)
    const float* __restrict__ boxes,    // (B, N, 5)
    float* __restrict__ out,            // (B, N, C, H_OUT, MAX_W)
    float* __restrict__ maskf,          // (B, N, MAX_W) as float, or null
    unsigned char* __restrict__ masku8) // (B, N, MAX_W) as u8, or null
{
    const int bi   = blockIdx.x;          // 0 .. B*N*H_OUT*2-1
    const int half = bi & 1;              // channel half
    const int i    = (bi >> 1) & (H_OUT_ - 1);
    const int bn   = bi >> 5;             // b*NBOX + n
    const int b    = bn >> 6;
    const int j    = threadIdx.x;

    const float* bx = boxes + bn * 5;
    const float left = bx[0];
    const float top  = bx[1];
    const float bw   = bx[2] - left;
    const float bh   = bx[3] - top;

    // width = int32(bw/bh * H_OUT): IEEE-correct division so truncation
    // matches the JAX reference bit-exactly (mask is binary!)
    const int   width  = (int)(__fdiv_rn(bw, bh) * (float)H_OUT_);
    const float each_w = __fdiv_rn(bw, (float)(width - 1));
    const float each_h = __fdiv_rn(bh, (float)(H_OUT_ - 1));

    const bool valid = (j < width);

    // out index (32-bit: max 25,165,824 < 2^31):
    // ((bn*C + c)*H_OUT + i)*MAX_W + j  with c = half*CHALF + cc
    const int cstride = H_OUT_ * MAX_W_;
    const int obase   = (bn * CC + half * CHALF) * cstride + i * MAX_W_ + j;

    if (i == 0 && half == 0) {
        if (maskf)  maskf [bn * MAX_W_ + j] = valid ? 1.0f : 0.0f;
        if (masku8) masku8[bn * MAX_W_ + j] = valid ? (unsigned char)1 : (unsigned char)0;
    }

    if (!valid) {
        #pragma unroll
        for (int cc = 0; cc < CHALF; cc++)
            out[obase + cc * cstride] = 0.0f;
        return;
    }

    const float x = (float)j * each_w + left;
    const float y = (float)i * each_h + top;
    int x0 = (int)floorf(x);
    int y0 = (int)floorf(y);
    int x1 = x0 + 1;
    int y1 = y0 + 1;
    x0 = max(0, min(x0, WW - 1));
    x1 = max(0, min(x1, WW - 1));
    y0 = max(0, min(y0, HH - 1));
    y1 = max(0, min(y1, HH - 1));

    const float wxl = (float)x1 - x;
    const float wxr = x - (float)x0;
    const float wyt = (float)y1 - y;
    const float wyb = y - (float)y0;

    const float wa = wxl * wyt;
    const float wb = wxl * wyb;
    const float wc = wxr * wyt;
    const float wd = wxr * wyb;

    const int o00 = y0 * WW + x0;
    const int dx  = x1 - x0;          // 0 or 1
    const int dy  = (y1 - y0) * WW;   // 0 or WW

    const float* p = img + b * (CC * HW) + (half * CHALF) * HW + o00;

    #pragma unroll
    for (int cc = 0; cc < CHALF; cc += 2) {
        const float* p0 = p;
        const float* p1 = p + HW;
        // issue all 8 independent gathers before any consume (MLP ~8)
        const float a0 = __ldg(p0);
        const float c0 = __ldg(p0 + dx);
        const float b0 = __ldg(p0 + dy);
        const float d0 = __ldg(p0 + dy + dx);
        const float a1 = __ldg(p1);
        const float c1 = __ldg(p1 + dx);
        const float b1 = __ldg(p1 + dy);
        const float d1 = __ldg(p1 + dy + dx);

        out[obase +  cc      * cstride] = a0 * wa + b0 * wb + c0 * wc + d0 * wd;
        out[obase + (cc + 1) * cstride] = a1 * wa + b1 * wb + c1 * wc + d1 * wd;
        p += 2 * HW;
    }
}

extern "C" void kernel_launch(void* const* d_in, const int* in_sizes, int n_in,
                              void* d_out, int out_size)
{
    const float* img   = (const float*)d_in[0];
    const float* boxes = (const float*)d_in[1];

    const long long R = (long long)BB * NBOX * CC * H_OUT_ * MAX_W_; // 25,165,824
    const long long M = (long long)BB * NBOX * MAX_W_;               // 49,152

    const dim3 grid(BB * NBOX * H_OUT_ * 2);  // 8192 blocks
    const dim3 block(MAX_W_);                 // 192 threads

    if ((long long)out_size == R * 4 + M) {
        unsigned char* ob = (unsigned char*)d_out;
        roirotate_kernel<<<grid, block>>>(img, boxes, (float*)ob, nullptr, ob + R * 4);
    } else if ((long long)out_size >= R + M) {
        float* of = (float*)d_out;
        roirotate_kernel<<<grid, block>>>(img, boxes, of, of + R, nullptr);
    } else {
        float* of = (float*)d_out;
        roirotate_kernel<<<grid, block>>>(img, boxes, of, nullptr, nullptr);
    }
}

// round 5
// speedup vs baseline: 1.0066x; 1.0066x over previous
#include <cuda_runtime.h>

#define BB     4
#define CC     32
#define HH     512
#define WW     512
#define NBOX   64
#define H_OUT_ 16
#define MAX_W_ 192
#define HW     (HH * WW)
#define CHALF  16
#define JSEG   64          // columns per block
#define NSEG   3           // MAX_W / JSEG

// Decomposition R5: one block per (bn, i, channel-half, j-segment).
// grid = (6, 16, 256) = 24576 blocks of 64 threads. Small blocks mean a
// narrow box's out-of-range segments retire almost immediately, freeing SM
// warp slots for gather-heavy blocks (width varies 12..192, ~48% of columns
// are masked). 32 CTAs/SM x 64 threads = 100% theoretical occupancy.
__global__ __launch_bounds__(JSEG) void roirotate_kernel(
    const float* __restrict__ img,      // (B, C, H, W)
    const float* __restrict__ boxes,    // (B, N, 5)
    float* __restrict__ out,            // (B, N, C, H_OUT, MAX_W)
    float* __restrict__ maskf,          // (B, N, MAX_W) as float, or null
    unsigned char* __restrict__ masku8) // (B, N, MAX_W) as u8, or null
{
    const int xs   = blockIdx.x;          // 0..5 : jseg*2 + half
    const int half = xs & 1;
    const int jseg = xs >> 1;             // 0..2
    const int i    = blockIdx.y;          // 0..15
    const int bn   = blockIdx.z;          // 0..255
    const int b    = bn >> 6;
    const int j    = jseg * JSEG + threadIdx.x;

    const float* bx = boxes + bn * 5;
    const float left = bx[0];
    const float top  = bx[1];
    const float bw   = bx[2] - left;
    const float bh   = bx[3] - top;

    // width = int32(bw/bh * H_OUT): IEEE-correct division so truncation
    // matches the JAX reference bit-exactly (mask is binary!)
    const int   width  = (int)(__fdiv_rn(bw, bh) * (float)H_OUT_);
    const float each_w = __fdiv_rn(bw, (float)(width - 1));
    const float each_h = __fdiv_rn(bh, (float)(H_OUT_ - 1));

    const bool valid = (j < width);

    // out index (32-bit: max 25,165,824 < 2^31):
    // ((bn*C + c)*H_OUT + i)*MAX_W + j  with c = half*CHALF + cc
    const int cstride = H_OUT_ * MAX_W_;
    const int obase   = (bn * CC + half * CHALF) * cstride + i * MAX_W_ + j;

    if (i == 0 && half == 0) {
        if (maskf)  maskf [bn * MAX_W_ + j] = valid ? 1.0f : 0.0f;
        if (masku8) masku8[bn * MAX_W_ + j] = valid ? (unsigned char)1 : (unsigned char)0;
    }

    if (!valid) {
        #pragma unroll
        for (int cc = 0; cc < CHALF; cc++)
            out[obase + cc * cstride] = 0.0f;
        return;
    }

    const float x = (float)j * each_w + left;
    const float y = (float)i * each_h + top;
    int x0 = (int)floorf(x);
    int y0 = (int)floorf(y);
    int x1 = x0 + 1;
    int y1 = y0 + 1;
    x0 = max(0, min(x0, WW - 1));
    x1 = max(0, min(x1, WW - 1));
    y0 = max(0, min(y0, HH - 1));
    y1 = max(0, min(y1, HH - 1));

    const float wxl = (float)x1 - x;
    const float wxr = x - (float)x0;
    const float wyt = (float)y1 - y;
    const float wyb = y - (float)y0;

    const float wa = wxl * wyt;
    const float wb = wxl * wyb;
    const float wc = wxr * wyt;
    const float wd = wxr * wyb;

    const int o00 = y0 * WW + x0;
    const int dx  = x1 - x0;          // 0 or 1
    const int dy  = (y1 - y0) * WW;   // 0 or WW

    const float* p = img + b * (CC * HW) + (half * CHALF) * HW + o00;

    #pragma unroll
    for (int cc = 0; cc < CHALF; cc++) {
        const float ia = __ldg(p);
        const float ic = __ldg(p + dx);
        const float ib = __ldg(p + dy);
        const float id = __ldg(p + dy + dx);
        out[obase + cc * cstride] = ia * wa + ib * wb + ic * wc + id * wd;
        p += HW;
    }
}

extern "C" void kernel_launch(void* const* d_in, const int* in_sizes, int n_in,
                              void* d_out, int out_size)
{
    const float* img   = (const float*)d_in[0];
    const float* boxes = (const float*)d_in[1];

    const long long R = (long long)BB * NBOX * CC * H_OUT_ * MAX_W_; // 25,165,824
    const long long M = (long long)BB * NBOX * MAX_W_;               // 49,152

    const dim3 grid(NSEG * 2, H_OUT_, BB * NBOX);  // (6, 16, 256) = 24576 blocks
    const dim3 block(JSEG);                        // 64 threads

    if ((long long)out_size == R * 4 + M) {
        unsigned char* ob = (unsigned char*)d_out;
        roirotate_kernel<<<grid, block>>>(img, boxes, (float*)ob, nullptr, ob + R * 4);
    } else if ((long long)out_size >= R + M) {
        float* of = (float*)d_out;
        roirotate_kernel<<<grid, block>>>(img, boxes, of, of + R, nullptr);
    } else {
        float* of = (float*)d_out;
        roirotate_kernel<<<grid, block>>>(img, boxes, of, nullptr, nullptr);
    }
}